// round 2
// baseline (speedup 1.0000x reference)
#include <cuda_runtime.h>

#define B_ 2
#define L_ 24
#define C_ 16
#define H_ 64
#define W_ 64
#define HW_ 4096

// Scratch: cumulative flows interleaved [b][l][p][2], channel-last images [b][l][p][c]
__device__ float g_cum[B_ * L_ * HW_ * 2];                    // 3 MB
__device__ float g_imgt[(size_t)B_ * L_ * HW_ * C_];          // 12.6 MB

// ---------------------------------------------------------------------------
// Kernel 1: cumulative sum of flows along L, stored as float2 (x,y) per pixel.
// flows layout: [B][L][2][H][W]
// ---------------------------------------------------------------------------
__global__ void cumsum_kernel(const float* __restrict__ flows) {
    int idx = blockIdx.x * blockDim.x + threadIdx.x;  // over B*HW
    if (idx >= B_ * HW_) return;
    int b = idx >> 12;
    int p = idx & (HW_ - 1);
    const float* f = flows + (size_t)b * L_ * 2 * HW_;
    float2* cum = (float2*)g_cum;
    float s0 = 0.0f, s1 = 0.0f;
#pragma unroll
    for (int l = 0; l < L_; l++) {
        s0 += f[(l * 2 + 0) * HW_ + p];
        s1 += f[(l * 2 + 1) * HW_ + p];
        cum[(b * L_ + l) * HW_ + p] = make_float2(s0, s1);
    }
}

// ---------------------------------------------------------------------------
// Kernel 2: transpose images [B][L][C][H][W] -> channel-last [B][L][HW][C]
// so one bilinear corner = 64 contiguous bytes (4x float4).
// ---------------------------------------------------------------------------
__global__ void transpose_kernel(const float* __restrict__ images) {
    int idx = blockIdx.x * blockDim.x + threadIdx.x;  // over B*L*HW
    if (idx >= B_ * L_ * HW_) return;
    int bl = idx >> 12;
    int p = idx & (HW_ - 1);
    const float* src = images + (size_t)bl * C_ * HW_ + p;
    float4* dst = (float4*)(g_imgt + ((size_t)bl * HW_ + p) * C_);
#pragma unroll
    for (int qq = 0; qq < 4; qq++) {
        float4 v;
        v.x = src[(qq * 4 + 0) * HW_];
        v.y = src[(qq * 4 + 1) * HW_];
        v.z = src[(qq * 4 + 2) * HW_];
        v.w = src[(qq * 4 + 3) * HW_];
        dst[qq] = v;
    }
}

// ---------------------------------------------------------------------------
// Kernel 3: main gather+accumulate.
// Block = (row y, target t, batch b). 256 threads = 64 pixels x 4 channel-quads.
// Each thread accumulates 4 channels of one pixel over k = 0..t.
// Lanes (pix, q): 4 consecutive lanes cover the full 64B of one source pixel,
// so a warp's corner load is ~512 contiguous bytes -> few L1 wavefronts.
// ---------------------------------------------------------------------------
__global__ __launch_bounds__(256) void warp_kernel(float* __restrict__ out) {
    int tid = threadIdx.x;
    int q = tid & 3;        // channel quad 0..3 (channels 4q..4q+3)
    int xpix = tid >> 2;    // 0..63
    int y = blockIdx.x;     // row 0..63
    int t = (L_ - 1) - (int)blockIdx.y;  // longest blocks launch first
    int b = blockIdx.z;
    int p = y * W_ + xpix;

    // pixel-center base grid (align_corners=False)
    float bx = -1.0f + (float)(2 * xpix + 1) * (1.0f / W_);
    float by = -1.0f + (float)(2 * y + 1) * (1.0f / H_);

    const float2* cum = (const float2*)g_cum;
    float2 ct = cum[(b * L_ + t) * HW_ + p];

    float4 acc = make_float4(0.0f, 0.0f, 0.0f, 0.0f);

    for (int k = 0; k <= t; k++) {
        float2 ck = cum[(b * L_ + k) * HW_ + p];
        float gx = bx + (ct.x - ck.x);
        float gy = by + (ct.y - ck.y);

        // wrap x into [-1, 1): remainder(gx + 1, 2) - 1
        float r = fmodf(gx + 1.0f, 2.0f);
        if (r < 0.0f) r += 2.0f;
        gx = r - 1.0f;

        float ix = (gx + 1.0f) * (W_ * 0.5f) - 0.5f;
        float iy = (gy + 1.0f) * (H_ * 0.5f) - 0.5f;
        float x0f = floorf(ix), y0f = floorf(iy);
        float wx1 = ix - x0f, wy1 = iy - y0f;
        float wx0 = 1.0f - wx1, wy0 = 1.0f - wy1;
        int x0 = (int)x0f, y0i = (int)y0f;
        int x1 = x0 + 1, y1i = y0i + 1;

        float vx0 = (x0 >= 0 && x0 <= W_ - 1) ? 1.0f : 0.0f;
        float vx1 = (x1 >= 0 && x1 <= W_ - 1) ? 1.0f : 0.0f;
        float vy0 = (y0i >= 0 && y0i <= H_ - 1) ? 1.0f : 0.0f;
        float vy1 = (y1i >= 0 && y1i <= H_ - 1) ? 1.0f : 0.0f;

        float w00 = wx0 * wy0 * vx0 * vy0;
        float w10 = wx1 * wy0 * vx1 * vy0;
        float w01 = wx0 * wy1 * vx0 * vy1;
        float w11 = wx1 * wy1 * vx1 * vy1;

        int x0c = min(max(x0, 0), W_ - 1);
        int x1c = min(max(x1, 0), W_ - 1);
        int y0c = min(max(y0i, 0), H_ - 1);
        int y1c = min(max(y1i, 0), H_ - 1);

        const float4* src =
            (const float4*)(g_imgt + ((size_t)(b * L_ + k) * HW_) * C_) + q;
        float4 s00 = src[(y0c * W_ + x0c) * 4];
        float4 s10 = src[(y0c * W_ + x1c) * 4];
        float4 s01 = src[(y1c * W_ + x0c) * 4];
        float4 s11 = src[(y1c * W_ + x1c) * 4];

        acc.x += w00 * s00.x + w10 * s10.x + w01 * s01.x + w11 * s11.x;
        acc.y += w00 * s00.y + w10 * s10.y + w01 * s01.y + w11 * s11.y;
        acc.z += w00 * s00.z + w10 * s10.z + w01 * s01.z + w11 * s11.z;
        acc.w += w00 * s00.w + w10 * s10.w + w01 * s01.w + w11 * s11.w;
    }

    // out layout [B][L][C][H][W]
    float* op = out + (((size_t)(b * L_ + t) * C_ + q * 4) * HW_) + p;
    op[0 * HW_] = acc.x;
    op[1 * HW_] = acc.y;
    op[2 * HW_] = acc.z;
    op[3 * HW_] = acc.w;
}

extern "C" void kernel_launch(void* const* d_in, const int* in_sizes, int n_in,
                              void* d_out, int out_size) {
    const float* flows = (const float*)d_in[0];
    const float* images = (const float*)d_in[1];
    float* out = (float*)d_out;

    cumsum_kernel<<<(B_ * HW_ + 255) / 256, 256>>>(flows);
    transpose_kernel<<<(B_ * L_ * HW_ + 255) / 256, 256>>>(images);
    dim3 grid(H_, L_, B_);
    warp_kernel<<<grid, 256>>>(out);
}

// round 3
// speedup vs baseline: 1.0611x; 1.0611x over previous
#include <cuda_runtime.h>

#define B_ 2
#define L_ 24
#define C_ 16
#define H_ 64
#define W_ 64
#define HW_ 4096

// Channel-last images [b][l][p][c]
__device__ float g_imgt[(size_t)B_ * L_ * HW_ * C_];          // 12.6 MB

// ---------------------------------------------------------------------------
// Kernel 1: transpose images [B][L][C][H][W] -> channel-last [B][L][HW][C].
// Shared-memory tiled: reads and writes are both fully coalesced 128B.
// Block = 256 threads, handles 128 pixels of one (b,l).
// ---------------------------------------------------------------------------
#define TP_PIX 128
__global__ __launch_bounds__(256) void transpose_kernel(const float* __restrict__ images) {
    __shared__ float s[TP_PIX][C_ + 1];   // +1 pad: conflict-free both phases
    int bl = blockIdx.x >> 5;             // 4096/128 = 32 blocks per (b,l)
    int p0 = (blockIdx.x & 31) * TP_PIX;
    const float* src = images + (size_t)bl * C_ * HW_ + p0;
    int tid = threadIdx.x;
#pragma unroll
    for (int it = 0; it < (TP_PIX * C_) / 256; ++it) {
        int e = it * 256 + tid;
        int c = e >> 7;          // channel
        int px = e & (TP_PIX - 1);
        s[px][c] = src[c * HW_ + px];      // coalesced 128B read per warp
    }
    __syncthreads();
    float* dst = g_imgt + ((size_t)bl * HW_ + p0) * C_;
#pragma unroll
    for (int it = 0; it < (TP_PIX * C_) / 256; ++it) {
        int f = it * 256 + tid;
        dst[f] = s[f >> 4][f & (C_ - 1)];  // coalesced 128B write per warp
    }
}

// ---------------------------------------------------------------------------
// Kernel 2: main gather+accumulate with in-loop flow reconstruction.
// Block = (row y, target t, batch b). 256 threads = 64 pixels x 4 channel-quads.
// k iterates DESCENDING from t; rel(k-1) = rel(k) + f_k, rel(t) = 0.
// 4 consecutive lanes cover the 64B of one source pixel -> warp corner load
// is ~512B contiguous.
// ---------------------------------------------------------------------------
__global__ __launch_bounds__(256) void warp_kernel(const float* __restrict__ flows,
                                                   float* __restrict__ out) {
    int tid = threadIdx.x;
    int q = tid & 3;        // channel quad
    int xpix = tid >> 2;    // 0..63
    int y = blockIdx.x;
    int t = (L_ - 1) - (int)blockIdx.y;   // longest blocks first
    int b = blockIdx.z;
    int p = y * W_ + xpix;

    // pixel-center base grid (align_corners=False)
    float bx = -1.0f + (float)(2 * xpix + 1) * (1.0f / W_);
    float by = -1.0f + (float)(2 * y + 1) * (1.0f / H_);

    const float* fbase = flows + (size_t)(b * L_) * 2 * HW_ + p;

    float relx = 0.0f, rely = 0.0f;
    float4 acc = make_float4(0.0f, 0.0f, 0.0f, 0.0f);

#pragma unroll 2
    for (int k = t; k >= 0; --k) {
        // prefetch flow f_k (used to advance rel after sampling)
        float fx = 0.0f, fy = 0.0f;
        if (k > 0) {
            fx = fbase[(2 * k) * HW_];
            fy = fbase[(2 * k + 1) * HW_];
        }

        float gx = bx + relx;
        float gy = by + rely;

        // wrap x into [-1,1): remainder(gx+1, 2) - 1, via floor
        float u = gx + 1.0f;
        u = u - 2.0f * floorf(u * 0.5f);          // in [0,2)
        float ix = fmaf(u, (float)(W_ / 2), -0.5f);
        float iy = fmaf(gy, (float)(H_ / 2), (float)(H_ / 2) - 0.5f);

        float x0f = floorf(ix), y0f = floorf(iy);
        float wx1 = ix - x0f, wy1 = iy - y0f;
        float wx0 = 1.0f - wx1, wy0 = 1.0f - wy1;
        int x0 = (int)x0f, y0i = (int)y0f;
        int x1 = x0 + 1, y1i = y0i + 1;

        float vx0 = (x0 >= 0 && x0 <= W_ - 1) ? 1.0f : 0.0f;
        float vx1 = (x1 >= 0 && x1 <= W_ - 1) ? 1.0f : 0.0f;
        float vy0 = (y0i >= 0 && y0i <= H_ - 1) ? 1.0f : 0.0f;
        float vy1 = (y1i >= 0 && y1i <= H_ - 1) ? 1.0f : 0.0f;

        float w00 = wx0 * wy0 * vx0 * vy0;
        float w10 = wx1 * wy0 * vx1 * vy0;
        float w01 = wx0 * wy1 * vx0 * vy1;
        float w11 = wx1 * wy1 * vx1 * vy1;

        int x0c = min(max(x0, 0), W_ - 1);
        int x1c = min(max(x1, 0), W_ - 1);
        int y0c = min(max(y0i, 0), H_ - 1);
        int y1c = min(max(y1i, 0), H_ - 1);

        const float4* src =
            (const float4*)(g_imgt + ((size_t)(b * L_ + k) * HW_) * C_) + q;
        float4 s00 = src[(y0c * W_ + x0c) * 4];
        float4 s10 = src[(y0c * W_ + x1c) * 4];
        float4 s01 = src[(y1c * W_ + x0c) * 4];
        float4 s11 = src[(y1c * W_ + x1c) * 4];

        acc.x += w00 * s00.x + w10 * s10.x + w01 * s01.x + w11 * s11.x;
        acc.y += w00 * s00.y + w10 * s10.y + w01 * s01.y + w11 * s11.y;
        acc.z += w00 * s00.z + w10 * s10.z + w01 * s01.z + w11 * s11.z;
        acc.w += w00 * s00.w + w10 * s10.w + w01 * s01.w + w11 * s11.w;

        relx += fx;
        rely += fy;
    }

    // out layout [B][L][C][H][W]
    float* op = out + (((size_t)(b * L_ + t) * C_ + q * 4) * HW_) + p;
    op[0 * HW_] = acc.x;
    op[1 * HW_] = acc.y;
    op[2 * HW_] = acc.z;
    op[3 * HW_] = acc.w;
}

extern "C" void kernel_launch(void* const* d_in, const int* in_sizes, int n_in,
                              void* d_out, int out_size) {
    const float* flows = (const float*)d_in[0];
    const float* images = (const float*)d_in[1];
    float* out = (float*)d_out;

    transpose_kernel<<<B_ * L_ * (HW_ / TP_PIX), 256>>>(images);
    dim3 grid(H_, L_, B_);
    warp_kernel<<<grid, 256>>>(flows, out);
}

// round 7
// speedup vs baseline: 1.0853x; 1.0228x over previous
#include <cuda_runtime.h>
#include <cuda_fp16.h>

#define B_ 2
#define L_ 24
#define C_ 16
#define H_ 64
#define W_ 64
#define HW_ 4096

// Channel-last fp16 images [b][l][p][c] : 6.3 MB
__device__ __half g_imgh[(size_t)B_ * L_ * HW_ * C_];

// ---------------------------------------------------------------------------
// Kernel 1: transpose+convert [B][L][C][HW] fp32 -> [B][L][HW][C] fp16.
// smem tiled; both GMEM phases fully coalesced.
// ---------------------------------------------------------------------------
__global__ __launch_bounds__(256) void transpose_kernel(const float* __restrict__ images) {
    __shared__ float s[128][C_ + 1];
    int bl = blockIdx.x >> 5;              // 32 blocks per (b,l)
    int p0 = (blockIdx.x & 31) * 128;
    const float* src = images + (size_t)bl * C_ * HW_ + p0;
    int tid = threadIdx.x;
#pragma unroll
    for (int it = 0; it < 8; ++it) {
        int e = it * 256 + tid;
        int c = e >> 7;
        int px = e & 127;
        s[px][c] = src[c * HW_ + px];      // 128B coalesced reads
    }
    __syncthreads();
    __half2* dst = (__half2*)(g_imgh + ((size_t)bl * HW_ + p0) * C_);
#pragma unroll
    for (int it = 0; it < 4; ++it) {
        int e = it * 256 + tid;            // half2 index = px*8 + cpair
        int px = e >> 3;
        int cp = e & 7;
        dst[e] = __floats2half2_rn(s[px][2 * cp], s[px][2 * cp + 1]);  // coalesced writes
    }
}

// ---------------------------------------------------------------------------
// Accumulate one corner: 16 fp16 channels (two uint4 regs) * weight into fp32 acc.
// ---------------------------------------------------------------------------
__device__ __forceinline__ void accum16(float* acc, uint4 a, uint4 b, float w) {
    unsigned wds[8] = {a.x, a.y, a.z, a.w, b.x, b.y, b.z, b.w};
#pragma unroll
    for (int j = 0; j < 8; ++j) {
        __half2 h = *(__half2*)&wds[j];
        float2 f = __half22float2(h);
        acc[2 * j]     = fmaf(w, f.x, acc[2 * j]);
        acc[2 * j + 1] = fmaf(w, f.y, acc[2 * j + 1]);
    }
}

// ---------------------------------------------------------------------------
// Kernel 2: main gather. 1 lane = 1 pixel, all 16 channels.
// Block = 128 threads = 2 rows x 64 px. Grid (32, 24, 2); t descending so the
// longest k-loops schedule first. rel flow reconstructed in-loop (k descending).
// ---------------------------------------------------------------------------
__global__ __launch_bounds__(128) void warp_kernel(const float* __restrict__ flows,
                                                   float* __restrict__ out) {
    int tid = threadIdx.x;
    int x = tid & 63;
    int y = (blockIdx.x << 1) + (tid >> 6);
    int t = (L_ - 1) - (int)blockIdx.y;
    int b = blockIdx.z;
    int p = (y << 6) + x;

    float ax = (float)(2 * x + 1) * (1.0f / 64.0f);  // (bx + 1), pre-wrap
    float yf = (float)y;                              // iy = rely*32 + y

    const float* fptr = flows + ((size_t)(b * L_ + t) * 2) * HW_ + p;
    const __half* ibase = g_imgh + (size_t)(b * L_ + t) * HW_ * C_;

    float relx = 0.0f, rely = 0.0f;
    float acc[C_];
#pragma unroll
    for (int c = 0; c < C_; ++c) acc[c] = 0.0f;

    for (int k = t; k >= 0; --k) {
        float fx = 0.0f, fy = 0.0f;
        if (k > 0) { fx = fptr[0]; fy = fptr[HW_]; }   // prefetch flow_k

        // wrap x: u = (gx+1) mod 2 (floor-mod), ix = u*32 - 0.5 in [-0.5, 63.5)
        float u0 = ax + relx;
        float u = u0 - 2.0f * floorf(0.5f * u0);
        float ixf = fmaf(u, 32.0f, -0.5f);
        float iyf = fmaf(rely, 32.0f, yf);

        float x0f = floorf(ixf), y0f = floorf(iyf);
        float wx1 = ixf - x0f, wy1 = iyf - y0f;
        float wx0 = 1.0f - wx1, wy0 = 1.0f - wy1;
        int x0 = (int)x0f, y0 = (int)y0f;

        // validity folded into weights (x wrapped => x0 in [-1,63])
        if (x0 < 0) wx0 = 0.0f;
        if (x0 > 62) wx1 = 0.0f;
        if ((unsigned)y0 > 63u) wy0 = 0.0f;
        if ((unsigned)(y0 + 1) > 63u) wy1 = 0.0f;

        float w00 = wx0 * wy0, w10 = wx1 * wy0;
        float w01 = wx0 * wy1, w11 = wx1 * wy1;

        int x0c = max(x0, 0), x1c = min(x0 + 1, 63);
        int y0c = min(max(y0, 0), 63), y1c = min(max(y0 + 1, 0), 63);

        const uint4* r0 = (const uint4*)(ibase + ((y0c << 6) + x0c) * C_);
        const uint4* r1 = (const uint4*)(ibase + ((y0c << 6) + x1c) * C_);
        const uint4* r2 = (const uint4*)(ibase + ((y1c << 6) + x0c) * C_);
        const uint4* r3 = (const uint4*)(ibase + ((y1c << 6) + x1c) * C_);

        // batch all 8 loads for MLP
        uint4 a00 = r0[0], b00 = r0[1];
        uint4 a10 = r1[0], b10 = r1[1];
        uint4 a01 = r2[0], b01 = r2[1];
        uint4 a11 = r3[0], b11 = r3[1];

        accum16(acc, a00, b00, w00);
        accum16(acc, a10, b10, w10);
        accum16(acc, a01, b01, w01);
        accum16(acc, a11, b11, w11);

        relx += fx;
        rely += fy;
        fptr -= 2 * HW_;
        ibase -= (size_t)HW_ * C_;
    }

    // out layout [B][L][C][H][W]; warp writes 128B coalesced per channel
    float* op = out + ((size_t)(b * L_ + t) * C_) * HW_ + p;
#pragma unroll
    for (int c = 0; c < C_; ++c) op[c * HW_] = acc[c];
}

extern "C" void kernel_launch(void* const* d_in, const int* in_sizes, int n_in,
                              void* d_out, int out_size) {
    const float* flows = (const float*)d_in[0];
    const float* images = (const float*)d_in[1];
    float* out = (float*)d_out;

    transpose_kernel<<<B_ * L_ * 32, 256>>>(images);
    dim3 grid(32, L_, B_);
    warp_kernel<<<grid, 128>>>(flows, out);
}

// round 8
// speedup vs baseline: 1.4638x; 1.3487x over previous
#include <cuda_runtime.h>
#include <cuda_fp16.h>

#define B_ 2
#define L_ 24
#define C_ 16
#define H_ 64
#define W_ 64
#define HW_ 4096

// fp16 images, layout [b][l][cq(2)][HW][8ch] : 16 B per (pixel, channel-oct)
__device__ __half g_imgh[(size_t)B_ * L_ * 2 * HW_ * 8];

// ---------------------------------------------------------------------------
// Kernel 1: repack [B][L][C][HW] fp32 -> [b][l][cq][HW][8] fp16.
// Thread = one (bl, cq, pixel): 8 coalesced 4B reads, one coalesced 16B write.
// ---------------------------------------------------------------------------
__global__ __launch_bounds__(256) void transpose_kernel(const float* __restrict__ images) {
    int idx = blockIdx.x * blockDim.x + threadIdx.x;   // over B*L*2*HW
    int p = idx & (HW_ - 1);
    int cq = (idx >> 12) & 1;
    int bl = idx >> 13;
    const float* src = images + ((size_t)bl * C_ + cq * 8) * HW_ + p;
    __half2 h[4];
#pragma unroll
    for (int j = 0; j < 4; ++j)
        h[j] = __floats2half2_rn(src[(2 * j) * HW_], src[(2 * j + 1) * HW_]);
    ((uint4*)g_imgh)[idx] = *(uint4*)h;
}

// ---------------------------------------------------------------------------
// Accumulate 8 fp16 channels (one uint4) * weight into fp32 acc.
// ---------------------------------------------------------------------------
__device__ __forceinline__ void accum8(float* acc, uint4 a, float w) {
    unsigned wds[4] = {a.x, a.y, a.z, a.w};
#pragma unroll
    for (int j = 0; j < 4; ++j) {
        float2 f = __half22float2(*(__half2*)&wds[j]);
        acc[2 * j]     = fmaf(w, f.x, acc[2 * j]);
        acc[2 * j + 1] = fmaf(w, f.y, acc[2 * j + 1]);
    }
}

// ---------------------------------------------------------------------------
// Kernel 2: main gather. 1 lane = 1 pixel, all 16 channels.
// Block = 128 threads = 2 rows x 64 px. Grid (32, 24, 2), t descending.
// rel flow reconstructed in-loop (k descending): rel(k-1) = rel(k) + f_k.
// Corner load = LDG.128 of 8 channels; warp spans 512B = 4 L1 lines.
// ---------------------------------------------------------------------------
__global__ __launch_bounds__(128, 8) void warp_kernel(const float* __restrict__ flows,
                                                      float* __restrict__ out) {
    int tid = threadIdx.x;
    int x = tid & 63;
    int y = (blockIdx.x << 1) + (tid >> 6);
    int t = (L_ - 1) - (int)blockIdx.y;
    int b = blockIdx.z;
    int p = (y << 6) + x;

    float ax = (float)(2 * x + 1) * (1.0f / 64.0f);  // (bx + 1), pre-wrap
    float yf = (float)y;                              // iy = rely*32 + y

    const float* fptr = flows + ((size_t)(b * L_ + t) * 2) * HW_ + p;
    const __half* ibase = g_imgh + (size_t)(b * L_ + t) * 2 * HW_ * 8;

    float relx = 0.0f, rely = 0.0f;
    float acc[C_];
#pragma unroll
    for (int c = 0; c < C_; ++c) acc[c] = 0.0f;

    for (int k = t; k >= 0; --k) {
        float fx = 0.0f, fy = 0.0f;
        if (k > 0) { fx = fptr[0]; fy = fptr[HW_]; }   // prefetch flow_k

        // wrap x: u = (gx+1) mod 2, ix = u*32 - 0.5 in [-0.5, 63.5)
        float u0 = ax + relx;
        float u = u0 - 2.0f * floorf(0.5f * u0);
        float ixf = fmaf(u, 32.0f, -0.5f);
        float iyf = fmaf(rely, 32.0f, yf);

        float x0f = floorf(ixf), y0f = floorf(iyf);
        float wx1 = ixf - x0f, wy1 = iyf - y0f;
        float wx0 = 1.0f - wx1, wy0 = 1.0f - wy1;
        int x0 = (int)x0f, y0 = (int)y0f;

        // validity folded into weights (x wrapped => x0 in [-1,63])
        if (x0 < 0) wx0 = 0.0f;
        if (x0 > 62) wx1 = 0.0f;
        if ((unsigned)y0 > 63u) wy0 = 0.0f;
        if ((unsigned)(y0 + 1) > 63u) wy1 = 0.0f;

        float w00 = wx0 * wy0, w10 = wx1 * wy0;
        float w01 = wx0 * wy1, w11 = wx1 * wy1;

        int x0c = max(x0, 0), x1c = min(x0 + 1, 63);
        int y0c = min(max(y0, 0), 63), y1c = min(max(y0 + 1, 0), 63);
        int p00 = (y0c << 6) + x0c, p10 = (y0c << 6) + x1c;
        int p01 = (y1c << 6) + x0c, p11 = (y1c << 6) + x1c;

        const uint4* lo = (const uint4*)ibase;          // cq = 0 (channels 0..7)
        const uint4* hi = lo + HW_;                     // cq = 1 (channels 8..15)

        // batch all 8 corner loads for MLP
        uint4 a00 = lo[p00], a10 = lo[p10], a01 = lo[p01], a11 = lo[p11];
        uint4 b00 = hi[p00], b10 = hi[p10], b01 = hi[p01], b11 = hi[p11];

        accum8(acc,     a00, w00); accum8(acc,     a10, w10);
        accum8(acc,     a01, w01); accum8(acc,     a11, w11);
        accum8(acc + 8, b00, w00); accum8(acc + 8, b10, w10);
        accum8(acc + 8, b01, w01); accum8(acc + 8, b11, w11);

        relx += fx;
        rely += fy;
        fptr -= 2 * HW_;
        ibase -= (size_t)2 * HW_ * 8;
    }

    // out layout [B][L][C][H][W]; warp writes 128B coalesced per channel
    float* op = out + ((size_t)(b * L_ + t) * C_) * HW_ + p;
#pragma unroll
    for (int c = 0; c < C_; ++c) op[c * HW_] = acc[c];
}

extern "C" void kernel_launch(void* const* d_in, const int* in_sizes, int n_in,
                              void* d_out, int out_size) {
    const float* flows = (const float*)d_in[0];
    const float* images = (const float*)d_in[1];
    float* out = (float*)d_out;

    transpose_kernel<<<(B_ * L_ * 2 * HW_) / 256, 256>>>(images);
    dim3 grid(32, L_, B_);
    warp_kernel<<<grid, 128>>>(flows, out);
}

// round 9
// speedup vs baseline: 1.4664x; 1.0018x over previous
#include <cuda_runtime.h>
#include <cuda_fp16.h>

#define B_ 2
#define L_ 24
#define C_ 16
#define H_ 64
#define W_ 64
#define HW_ 4096

// fp16 images, layout [b][l][cq(2)][HW][8ch] : 16 B per (pixel, channel-oct)
__device__ __half g_imgh[(size_t)B_ * L_ * 2 * HW_ * 8];

// ---------------------------------------------------------------------------
// Kernel 1: repack [B][L][C][HW] fp32 -> [b][l][cq][HW][8] fp16.
// ---------------------------------------------------------------------------
__global__ __launch_bounds__(256) void transpose_kernel(const float* __restrict__ images) {
    int idx = blockIdx.x * blockDim.x + threadIdx.x;   // over B*L*2*HW
    int p = idx & (HW_ - 1);
    int cq = (idx >> 12) & 1;
    int bl = idx >> 13;
    const float* src = images + ((size_t)bl * C_ + cq * 8) * HW_ + p;
    __half2 h[4];
#pragma unroll
    for (int j = 0; j < 4; ++j)
        h[j] = __floats2half2_rn(src[(2 * j) * HW_], src[(2 * j + 1) * HW_]);
    ((uint4*)g_imgh)[idx] = *(uint4*)h;
}

// ---------------------------------------------------------------------------
// Accumulate 8 fp16 channels (one uint4) * weight into fp32 acc.
// ---------------------------------------------------------------------------
__device__ __forceinline__ void accum8(float* acc, uint4 a, float w) {
    unsigned wds[4] = {a.x, a.y, a.z, a.w};
#pragma unroll
    for (int j = 0; j < 4; ++j) {
        float2 f = __half22float2(*(__half2*)&wds[j]);
        acc[2 * j]     = fmaf(w, f.x, acc[2 * j]);
        acc[2 * j + 1] = fmaf(w, f.y, acc[2 * j + 1]);
    }
}

// ---------------------------------------------------------------------------
// One t-phase: accumulate over k = t..0 and write out[b,t,:,row].
// ---------------------------------------------------------------------------
__device__ __forceinline__ void do_target(int b, int t, int x, int y, int p,
                                          float ax, float yf,
                                          const float* __restrict__ flows,
                                          float* __restrict__ out) {
    const float* fptr = flows + ((size_t)(b * L_ + t) * 2) * HW_ + p;
    const __half* ibase = g_imgh + (size_t)(b * L_ + t) * 2 * HW_ * 8;

    float relx = 0.0f, rely = 0.0f;
    float acc[C_];
#pragma unroll
    for (int c = 0; c < C_; ++c) acc[c] = 0.0f;

    for (int k = t; k >= 0; --k) {
        float fx = 0.0f, fy = 0.0f;
        if (k > 0) { fx = fptr[0]; fy = fptr[HW_]; }   // prefetch flow_k

        // wrap x: u = (gx+1) mod 2, ix = u*32 - 0.5 in [-0.5, 63.5)
        float u0 = ax + relx;
        float u = u0 - 2.0f * floorf(0.5f * u0);
        float ixf = fmaf(u, 32.0f, -0.5f);
        float iyf = fmaf(rely, 32.0f, yf);

        float x0f = floorf(ixf), y0f = floorf(iyf);
        float wx1 = ixf - x0f, wy1 = iyf - y0f;
        float wx0 = 1.0f - wx1, wy0 = 1.0f - wy1;
        int x0 = (int)x0f, y0 = (int)y0f;

        // validity folded into weights (x wrapped => x0 in [-1,63])
        if (x0 < 0) wx0 = 0.0f;
        if (x0 > 62) wx1 = 0.0f;
        if ((unsigned)y0 > 63u) wy0 = 0.0f;
        if ((unsigned)(y0 + 1) > 63u) wy1 = 0.0f;

        float w00 = wx0 * wy0, w10 = wx1 * wy0;
        float w01 = wx0 * wy1, w11 = wx1 * wy1;

        int x0c = max(x0, 0), x1c = min(x0 + 1, 63);
        int y0c = min(max(y0, 0), 63), y1c = min(max(y0 + 1, 0), 63);
        int p00 = (y0c << 6) + x0c, p10 = (y0c << 6) + x1c;
        int p01 = (y1c << 6) + x0c, p11 = (y1c << 6) + x1c;

        const uint4* lo = (const uint4*)ibase;          // cq = 0 (channels 0..7)
        const uint4* hi = lo + HW_;                     // cq = 1 (channels 8..15)

        // batch all 8 corner loads for MLP
        uint4 a00 = lo[p00], a10 = lo[p10], a01 = lo[p01], a11 = lo[p11];
        uint4 b00 = hi[p00], b10 = hi[p10], b01 = hi[p01], b11 = hi[p11];

        accum8(acc,     a00, w00); accum8(acc,     a10, w10);
        accum8(acc,     a01, w01); accum8(acc,     a11, w11);
        accum8(acc + 8, b00, w00); accum8(acc + 8, b10, w10);
        accum8(acc + 8, b01, w01); accum8(acc + 8, b11, w11);

        relx += fx;
        rely += fy;
        fptr -= 2 * HW_;
        ibase -= (size_t)2 * HW_ * 8;
    }

    // out layout [B][L][C][H][W]; warp writes 128B coalesced per channel
    float* op = out + ((size_t)(b * L_ + t) * C_) * HW_ + p;
#pragma unroll
    for (int c = 0; c < C_; ++c) op[c * HW_] = acc[c];
}

// ---------------------------------------------------------------------------
// Kernel 2: main gather. 1 lane = 1 pixel, all 16 channels.
// Block = 64 threads = 1 row. Grid (64, 12, 2).
// Perfect balance: blockIdx.y = i handles t1 = 23-i and t2 = i, so every
// block runs exactly (t1+1)+(t2+1) = 25 k-iterations. 1536 uniform blocks,
// ~10/SM, single wave.
// ---------------------------------------------------------------------------
__global__ __launch_bounds__(64) void warp_kernel(const float* __restrict__ flows,
                                                  float* __restrict__ out) {
    int x = threadIdx.x;            // 0..63
    int y = blockIdx.x;             // 0..63
    int i = blockIdx.y;             // 0..11
    int b = blockIdx.z;
    int p = (y << 6) + x;

    float ax = (float)(2 * x + 1) * (1.0f / 64.0f);  // (bx + 1), pre-wrap
    float yf = (float)y;                              // iy = rely*32 + y

    do_target(b, (L_ - 1) - i, x, y, p, ax, yf, flows, out);
    do_target(b, i,            x, y, p, ax, yf, flows, out);
}

extern "C" void kernel_launch(void* const* d_in, const int* in_sizes, int n_in,
                              void* d_out, int out_size) {
    const float* flows = (const float*)d_in[0];
    const float* images = (const float*)d_in[1];
    float* out = (float*)d_out;

    transpose_kernel<<<(B_ * L_ * 2 * HW_) / 256, 256>>>(images);
    dim3 grid(64, 12, B_);
    warp_kernel<<<grid, 64>>>(flows, out);
}